// round 8
// baseline (speedup 1.0000x reference)
#include <cuda_runtime.h>
#include <cuda_bf16.h>
#include <stdint.h>
#include <math.h>

// ---------------------------------------------------------------------------
// Problem constants
// ---------------------------------------------------------------------------
#define BB 4096
#define NN 19
#define EE 342
#define ET 361
#define FF 256
#define HH 512
#define OO 256
#define MM (BB * NN)      // 77824 = 608 * 128

// Quantization: v = sa * (128*a1 + a0), |q| <= 16256 = 127*128
#define QMAX 16256.0f

// ---------------------------------------------------------------------------
// Scratch (device globals)
// ---------------------------------------------------------------------------
__device__ signed char g_X1[(size_t)MM * FF];
__device__ signed char g_X0[(size_t)MM * FF];
__device__ signed char g_Aa1[(size_t)MM * HH];
__device__ signed char g_Aa0[(size_t)MM * HH];
__device__ signed char g_Ab1[(size_t)MM * HH];
__device__ signed char g_Ab0[(size_t)MM * HH];
__device__ float       g_H  [(size_t)MM * HH];
__device__ signed char g_W1[4][HH * HH];   // transposed weight digits [N,K]
__device__ signed char g_W0[4][HH * HH];
__device__ float g_saX[MM];
__device__ float g_saA[2][MM];
__device__ float g_sbW[4][HH];

// ---------------------------------------------------------------------------
// Helpers
// ---------------------------------------------------------------------------
__device__ __forceinline__ uint32_t smem_u32(const void* p) {
    uint32_t a;
    asm("{ .reg .u64 t; cvta.to.shared.u64 t, %1; cvt.u32.u64 %0, t; }"
        : "=r"(a) : "l"(p));
    return a;
}
#define SWZ(o) ((o) ^ (((o) >> 3) & 0x70))

__device__ __forceinline__ void cp16(uint32_t s, const void* g) {
    asm volatile("cp.async.cg.shared.global [%0], [%1], 16;" :: "r"(s), "l"(g));
}

__device__ __forceinline__ void atomicMaxF(float* addr, float v) {
    int* ai = (int*)addr;
    int old = __float_as_int(*addr);
    while (__int_as_float(old) < v) {
        int prev = atomicCAS(ai, old, __float_as_int(v));
        if (prev == old) break;
        old = prev;
    }
}

__device__ __forceinline__ void quant15(float v, float inv,
                                        signed char& d1, signed char& d0) {
    float q = v * inv;                               // |q| <= 16256
    int a1 = __float2int_rn(q * 0.0078125f);         // round(q/128), <=127
    int a0 = __float2int_rn(q - 128.f * (float)a1);  // in [-64, 64]
    d1 = (signed char)a1;
    d0 = (signed char)a0;
}

// ---------------------------------------------------------------------------
// Setup: quantize x (warp per row, coalesced) and W (warp per output col)
// ---------------------------------------------------------------------------
__global__ void __launch_bounds__(256) quant_x_kernel(
    const float* __restrict__ x, signed char* __restrict__ X1,
    signed char* __restrict__ X0, float* __restrict__ sa)
{
    int wid = threadIdx.x >> 5, lane = threadIdx.x & 31;
    int row = blockIdx.x * 8 + wid;
    const float* xr = x + (size_t)row * FF;
    float mx = 0.f;
#pragma unroll
    for (int j = 0; j < FF / 32; j++) mx = fmaxf(mx, fabsf(xr[lane + 32 * j]));
#pragma unroll
    for (int o = 16; o; o >>= 1) mx = fmaxf(mx, __shfl_xor_sync(0xffffffffu, mx, o));
    mx = fmaxf(mx, 1e-30f);
    float inv = QMAX / mx;
#pragma unroll
    for (int j = 0; j < FF / 32; j++) {
        int c = lane + 32 * j;
        signed char d1, d0;
        quant15(xr[c], inv, d1, d0);
        X1[(size_t)row * FF + c] = d1;
        X0[(size_t)row * FF + c] = d0;
    }
    if (lane == 0) sa[row] = mx / QMAX;
}

// W [K,N] fp32 -> digits [N,K] int8 + per-n scale
__global__ void __launch_bounds__(256) quant_w_kernel(
    const float* __restrict__ W, int K, int N,
    signed char* __restrict__ W1, signed char* __restrict__ W0,
    float* __restrict__ sb)
{
    int wid = threadIdx.x >> 5, lane = threadIdx.x & 31;
    int n = blockIdx.x * 8 + wid;
    if (n >= N) return;
    float mx = 0.f;
    for (int k = lane; k < K; k += 32) mx = fmaxf(mx, fabsf(W[(size_t)k * N + n]));
#pragma unroll
    for (int o = 16; o; o >>= 1) mx = fmaxf(mx, __shfl_xor_sync(0xffffffffu, mx, o));
    mx = fmaxf(mx, 1e-30f);
    float inv = QMAX / mx;
    for (int k = lane; k < K; k += 32) {
        signed char d1, d0;
        quant15(W[(size_t)k * N + n], inv, d1, d0);
        W1[(size_t)n * K + k] = d1;
        W0[(size_t)n * K + k] = d0;
    }
    if (lane == 0) sb[n] = mx / QMAX;
}

// ---------------------------------------------------------------------------
// int8 15-bit GEMM: H[M,NT] = dequant( A(digits,saA) @ B(digits,sbB) )
//   acc1 = A1*B1 ; acc2 = A1*B0 + A0*B1 ; C = sa*sb*(16384*acc1 + 128*acc2)
// A digits: [M,K] row-major int8.  B digits: [NT,K] (n-major, K contiguous).
// CTA tile 128x128, 8 warps (2M x 4N), warp tile 64x32.
// K-chunks of 128 (128B rows, XOR swizzle), 3-stage cp.async pipeline.
// ---------------------------------------------------------------------------
#define STG_SZ  65536     // A1 16K | A0 16K | B1 16K | B0 16K
#define OFF_SA  196608
#define OFF_SB  197120
#define DSMEM_G 197632

__device__ __forceinline__ void mma_s8(int* d, const uint32_t* a,
                                       uint32_t b0, uint32_t b1) {
    asm volatile(
        "mma.sync.aligned.m16n8k32.row.col.s32.s8.s8.s32 "
        "{%0,%1,%2,%3}, {%4,%5,%6,%7}, {%8,%9}, {%0,%1,%2,%3};"
        : "+r"(d[0]), "+r"(d[1]), "+r"(d[2]), "+r"(d[3])
        : "r"(a[0]), "r"(a[1]), "r"(a[2]), "r"(a[3]), "r"(b0), "r"(b1));
}

template <int K, int NT>
__global__ void __launch_bounds__(256, 1)
gemm_s8(const signed char* __restrict__ A1, const signed char* __restrict__ A0,
        const float* __restrict__ saA,
        const signed char* __restrict__ B1, const signed char* __restrict__ B0,
        const float* __restrict__ sbB,
        float* __restrict__ Hout)
{
    extern __shared__ char smem[];
    const uint32_t sb = smem_u32(smem);
    const int tid  = threadIdx.x;
    const int wid  = tid >> 5;
    const int lane = tid & 31;
    const int bm = blockIdx.y * 128;
    const int bn = blockIdx.x * 128;
    const int wm = wid & 1;        // 0..1 : 64-row halves
    const int wn = wid >> 1;       // 0..3 : 32-col quarters

    float* saS = (float*)(smem + OFF_SA);
    float* sbS = (float*)(smem + OFF_SB);

    constexpr int NCH = K / 128;   // K-chunks of 128 int8

    auto issue = [&](int ch) {
        const uint32_t st = sb + (uint32_t)(ch % 3) * STG_SZ;
        const int kb = ch * 128;
        const int r = tid >> 1, c = tid & 1;   // 128 rows x 2 16B-halves... (see below)
        // each buffer: 128 rows x 128B = 1024 x 16B units; 4 units/thread
#pragma unroll
        for (int i = 0; i < 4; i++) {
            int u = tid + i * 256;
            int rr = u >> 3, cc = u & 7;
            uint32_t so = SWZ((uint32_t)(rr * 128 + cc * 16));
            size_t goA = (size_t)(bm + rr) * K + kb + cc * 16;
            size_t goB = (size_t)(bn + rr) * K + kb + cc * 16;
            cp16(st + so,          A1 + goA);
            cp16(st + 16384u + so, A0 + goA);
            cp16(st + 32768u + so, B1 + goB);
            cp16(st + 49152u + so, B0 + goB);
        }
        (void)r; (void)c;
    };

    int acc1[4][4][4] = {};
    int acc2[4][4][4] = {};

    if (tid < 128) {
        saS[tid] = saA[bm + tid];
        sbS[tid] = sbB[bn + tid];
    }

    issue(0);
    asm volatile("cp.async.commit_group;" ::: "memory");
    if (NCH > 1) issue(1);
    asm volatile("cp.async.commit_group;" ::: "memory");

    for (int ch = 0; ch < NCH; ch++) {
        if (ch + 2 < NCH) {
            asm volatile("cp.async.wait_group 1;" ::: "memory");
            __syncthreads();
            issue(ch + 2);
            asm volatile("cp.async.commit_group;" ::: "memory");
        } else if (ch + 1 < NCH) {
            asm volatile("cp.async.wait_group 1;" ::: "memory");
            __syncthreads();
        } else {
            asm volatile("cp.async.wait_group 0;" ::: "memory");
            __syncthreads();
        }

        const uint32_t st  = sb + (uint32_t)(ch % 3) * STG_SZ;
        const uint32_t sA1 = st;
        const uint32_t sA0 = st + 16384u;
        const uint32_t sB1 = st + 32768u;
        const uint32_t sB0 = st + 49152u;
#pragma unroll
        for (int kk = 0; kk < 4; kk++) {       // k32 steps within k128 chunk
            // B fragments: warp's 32 cols -> per digit: 2 x4-ldmatrix (n16 x k32)
            uint32_t b1f[8], b0f[8];
#pragma unroll
            for (int g = 0; g < 2; g++) {
                int n = wn * 32 + g * 16 + ((lane >> 4) * 8) + (lane & 7);
                uint32_t so = SWZ((uint32_t)(n * 128 + kk * 32 + ((lane >> 3) & 1) * 16));
                asm volatile(
                    "ldmatrix.sync.aligned.m8n8.x4.shared.b16 {%0,%1,%2,%3}, [%4];"
                    : "=r"(b1f[g * 4 + 0]), "=r"(b1f[g * 4 + 1]),
                      "=r"(b1f[g * 4 + 2]), "=r"(b1f[g * 4 + 3])
                    : "r"(sB1 + so));
                asm volatile(
                    "ldmatrix.sync.aligned.m8n8.x4.shared.b16 {%0,%1,%2,%3}, [%4];"
                    : "=r"(b0f[g * 4 + 0]), "=r"(b0f[g * 4 + 1]),
                      "=r"(b0f[g * 4 + 2]), "=r"(b0f[g * 4 + 3])
                    : "r"(sB0 + so));
            }
#pragma unroll
            for (int mt = 0; mt < 4; mt++) {
                uint32_t a1f[4], a0f[4];
                int m = wm * 64 + mt * 16 + (lane & 15);
                uint32_t so = SWZ((uint32_t)(m * 128 + kk * 32 + (lane >> 4) * 16));
                asm volatile(
                    "ldmatrix.sync.aligned.m8n8.x4.shared.b16 {%0,%1,%2,%3}, [%4];"
                    : "=r"(a1f[0]), "=r"(a1f[1]), "=r"(a1f[2]), "=r"(a1f[3])
                    : "r"(sA1 + so));
                asm volatile(
                    "ldmatrix.sync.aligned.m8n8.x4.shared.b16 {%0,%1,%2,%3}, [%4];"
                    : "=r"(a0f[0]), "=r"(a0f[1]), "=r"(a0f[2]), "=r"(a0f[3])
                    : "r"(sA0 + so));
#pragma unroll
                for (int nt = 0; nt < 4; nt++) {
                    mma_s8(acc1[mt][nt], a1f, b1f[nt * 2], b1f[nt * 2 + 1]);
                    mma_s8(acc2[mt][nt], a1f, b0f[nt * 2], b0f[nt * 2 + 1]);
                    mma_s8(acc2[mt][nt], a0f, b1f[nt * 2], b1f[nt * 2 + 1]);
                }
            }
        }
        __syncthreads();
    }

    // Epilogue: dequantize + fp32 stores
#pragma unroll
    for (int mt = 0; mt < 4; mt++) {
        int lr = wm * 64 + mt * 16 + (lane >> 2);
        float s0 = saS[lr], s1 = saS[lr + 8];
#pragma unroll
        for (int nt = 0; nt < 4; nt++) {
            int lc = wn * 32 + nt * 8 + (lane & 3) * 2;
            float t0 = sbS[lc], t1 = sbS[lc + 1];
            int* d1 = acc1[mt][nt];
            int* d2 = acc2[mt][nt];
            float v00 = fmaf(16384.f, (float)d1[0], 128.f * (float)d2[0]) * s0 * t0;
            float v01 = fmaf(16384.f, (float)d1[1], 128.f * (float)d2[1]) * s0 * t1;
            float v10 = fmaf(16384.f, (float)d1[2], 128.f * (float)d2[2]) * s1 * t0;
            float v11 = fmaf(16384.f, (float)d1[3], 128.f * (float)d2[3]) * s1 * t1;
            *(float2*)(Hout + (size_t)(bm + lr) * NT + bn + lc)     = make_float2(v00, v01);
            *(float2*)(Hout + (size_t)(bm + lr + 8) * NT + bn + lc) = make_float2(v10, v11);
        }
    }
}

// ---------------------------------------------------------------------------
// Attention + aggregation (dense alpha) + int8 quantization epilogue.
// One CTA per graph, C threads. Softmax without max-subtraction.
// ---------------------------------------------------------------------------
template <int C>
__device__ __forceinline__ void attn_alpha(
    const float* __restrict__ hs, const int* __restrict__ ei,
    const float* __restrict__ a_s, const float* __restrict__ a_d,
    float* als, float* ald, float* nsum, float* alphaM, int t)
{
    {
        const int w = t >> 5, lane = t & 31, NW = C / 32;
        for (int n = w; n < NN; n += NW) {
            float s = 0.f, d = 0.f;
#pragma unroll
            for (int j = 0; j < C / 32; j++) {
                float h = hs[n * C + lane + 32 * j];
                s += h * __ldg(a_s + lane + 32 * j);
                d += h * __ldg(a_d + lane + 32 * j);
            }
#pragma unroll
            for (int o = 16; o; o >>= 1) {
                s += __shfl_xor_sync(0xffffffffu, s, o);
                d += __shfl_xor_sync(0xffffffffu, d, o);
            }
            if (lane == 0) { als[n] = s; ald[n] = d; }
        }
    }
    __syncthreads();
    for (int e = t; e < ET; e += C) {
        int se = (e < EE) ? ei[e] : (e - EE);
        int de = (e < EE) ? ei[EE + e] : (e - EE);
        float z = als[se] + ald[de];
        float lg = (z >= 0.f) ? z : 0.2f * z;
        atomicAdd(&nsum[de], __expf(lg));
    }
    __syncthreads();
    if (t < NN) nsum[t] = 1.f / nsum[t];
    __syncthreads();
    for (int e = t; e < ET; e += C) {
        int se = (e < EE) ? ei[e] : (e - EE);
        int de = (e < EE) ? ei[EE + e] : (e - EE);
        float z = als[se] + ald[de];
        float lg = (z >= 0.f) ? z : 0.2f * z;
        atomicAdd(&alphaM[de * NN + se], __expf(lg) * nsum[de]);
    }
    __syncthreads();
}

template <int C, bool RELU>
__global__ void __launch_bounds__(C) gat_agg_q(
    const float* __restrict__ H, const int* __restrict__ ei,
    const float* __restrict__ a_s, const float* __restrict__ a_d,
    const float* __restrict__ bias,
    signed char* __restrict__ O1, signed char* __restrict__ O0,
    float* __restrict__ saOut)
{
    __shared__ alignas(16) float hs[NN * C];
    __shared__ float als[NN], ald[NN], nsum[NN], rmax[NN];
    __shared__ float alphaM[NN * NN];

    const int t = threadIdx.x;
    const int lane = t & 31;
    const size_t gbase = (size_t)blockIdx.x * NN * C;

    if (t < NN) { nsum[t] = 0.f; rmax[t] = 0.f; }
    for (int i = t; i < NN * NN; i += C) alphaM[i] = 0.f;
    {
        const float4* H4 = (const float4*)(H + gbase);
        float4* hs4 = (float4*)hs;
        for (int i = t; i < NN * C / 4; i += C) hs4[i] = H4[i];
    }
    __syncthreads();

    attn_alpha<C>(hs, ei, a_s, a_d, als, ald, nsum, alphaM, t);

    float hreg[NN];
#pragma unroll
    for (int s = 0; s < NN; s++) hreg[s] = hs[s * C + t];
    const float bc = bias[t];

    float v[NN];
#pragma unroll
    for (int n = 0; n < NN; n++) {
        float acc = 0.f;
#pragma unroll
        for (int s = 0; s < NN; s++) acc += alphaM[n * NN + s] * hreg[s];
        float o = acc + bc;
        if (RELU) o = fmaxf(o, 0.f);
        v[n] = o;
    }

    // per-node rowmax
#pragma unroll
    for (int n = 0; n < NN; n++) {
        float m = fabsf(v[n]);
#pragma unroll
        for (int o = 16; o; o >>= 1) m = fmaxf(m, __shfl_xor_sync(0xffffffffu, m, o));
        if (lane == 0) atomicMaxF(&rmax[n], m);
    }
    __syncthreads();

    if (t < NN) saOut[(size_t)blockIdx.x * NN + t] = fmaxf(rmax[t], 1e-30f) / QMAX;
#pragma unroll
    for (int n = 0; n < NN; n++) {
        float inv = QMAX / fmaxf(rmax[n], 1e-30f);
        signed char d1, d0;
        quant15(v[n], inv, d1, d0);
        O1[gbase + (size_t)n * C + t] = d1;
        O0[gbase + (size_t)n * C + t] = d0;
    }
}

// Final layer: aggregation (no relu) + fused head
__global__ void __launch_bounds__(OO) gat_final(
    const float* __restrict__ H, const int* __restrict__ ei,
    const float* __restrict__ a_s, const float* __restrict__ a_d,
    const float* __restrict__ bias, float* __restrict__ outp,
    const float* __restrict__ ws, const float* __restrict__ bsc)
{
    constexpr int C = OO;
    __shared__ alignas(16) float hs[NN * C];
    __shared__ float als[NN], ald[NN], nsum[NN];
    __shared__ float alphaM[NN * NN];
    __shared__ alignas(16) float outbuf[NN * C];
    __shared__ float pbuf[C];

    const int t = threadIdx.x;
    const size_t gbase = (size_t)blockIdx.x * NN * C;

    if (t < NN) nsum[t] = 0.f;
    for (int i = t; i < NN * NN; i += C) alphaM[i] = 0.f;
    {
        const float4* H4 = (const float4*)(H + gbase);
        float4* hs4 = (float4*)hs;
        for (int i = t; i < NN * C / 4; i += C) hs4[i] = H4[i];
    }
    __syncthreads();

    attn_alpha<C>(hs, ei, a_s, a_d, als, ald, nsum, alphaM, t);

    float hreg[NN];
#pragma unroll
    for (int s = 0; s < NN; s++) hreg[s] = hs[s * C + t];
    const float bc = bias[t];
#pragma unroll
    for (int n = 0; n < NN; n++) {
        float acc = 0.f;
#pragma unroll
        for (int s = 0; s < NN; s++) acc += alphaM[n * NN + s] * hreg[s];
        outbuf[n * C + t] = acc + bc;
    }
    __syncthreads();

    {
        float pv = 0.f;
#pragma unroll
        for (int n = 0; n < NN; n++) pv += ws[n] * outbuf[n * C + t];
        pbuf[t] = pv;
    }
    __syncthreads();
    {
        const int w = t >> 5, lane = t & 31, NW = C / 32;
        const float bv = bsc[0];
        for (int n = w; n < NN; n += NW) {
            float s = 0.f;
#pragma unroll
            for (int j = 0; j < C / 32; j++)
                s += outbuf[n * C + lane + 32 * j] * pbuf[lane + 32 * j];
#pragma unroll
            for (int o = 16; o; o >>= 1)
                s += __shfl_xor_sync(0xffffffffu, s, o);
            if (lane == 0)
                outp[(size_t)blockIdx.x * NN + n] = 1.f / (1.f + __expf(-(s + bv)));
        }
    }
}

// ---------------------------------------------------------------------------
// Launch
// ---------------------------------------------------------------------------
extern "C" void kernel_launch(void* const* d_in, const int* in_sizes, int n_in,
                              void* d_out, int out_size)
{
    (void)in_sizes; (void)n_in; (void)out_size;
    const float* x   = (const float*)d_in[0];
    const int*   ei  = (const int*)  d_in[1];
    const float* W1  = (const float*)d_in[3];
    const float* as1 = (const float*)d_in[4];
    const float* ad1 = (const float*)d_in[5];
    const float* b1  = (const float*)d_in[6];
    const float* W2  = (const float*)d_in[7];
    const float* as2 = (const float*)d_in[8];
    const float* ad2 = (const float*)d_in[9];
    const float* b2  = (const float*)d_in[10];
    const float* W3  = (const float*)d_in[11];
    const float* as3 = (const float*)d_in[12];
    const float* ad3 = (const float*)d_in[13];
    const float* b3  = (const float*)d_in[14];
    const float* W4  = (const float*)d_in[15];
    const float* as4 = (const float*)d_in[16];
    const float* ad4 = (const float*)d_in[17];
    const float* b4  = (const float*)d_in[18];
    const float* ws  = (const float*)d_in[19];
    const float* bs  = (const float*)d_in[20];
    float* out = (float*)d_out;

    signed char *X1, *X0, *Aa1, *Aa0, *Ab1, *Ab0, *Wd1, *Wd0;
    float *Hb, *saX, *saA, *sbW;
    cudaGetSymbolAddress((void**)&X1,  g_X1);
    cudaGetSymbolAddress((void**)&X0,  g_X0);
    cudaGetSymbolAddress((void**)&Aa1, g_Aa1);
    cudaGetSymbolAddress((void**)&Aa0, g_Aa0);
    cudaGetSymbolAddress((void**)&Ab1, g_Ab1);
    cudaGetSymbolAddress((void**)&Ab0, g_Ab0);
    cudaGetSymbolAddress((void**)&Hb,  g_H);
    cudaGetSymbolAddress((void**)&Wd1, g_W1);
    cudaGetSymbolAddress((void**)&Wd0, g_W0);
    cudaGetSymbolAddress((void**)&saX, g_saX);
    cudaGetSymbolAddress((void**)&saA, g_saA);
    cudaGetSymbolAddress((void**)&sbW, g_sbW);

    cudaFuncSetAttribute(gemm_s8<FF, HH>, cudaFuncAttributeMaxDynamicSharedMemorySize, DSMEM_G);
    cudaFuncSetAttribute(gemm_s8<HH, HH>, cudaFuncAttributeMaxDynamicSharedMemorySize, DSMEM_G);
    cudaFuncSetAttribute(gemm_s8<HH, OO>, cudaFuncAttributeMaxDynamicSharedMemorySize, DSMEM_G);

    signed char* W1d[4] = { Wd1, Wd1 + (size_t)HH * HH, Wd1 + 2 * (size_t)HH * HH, Wd1 + 3 * (size_t)HH * HH };
    signed char* W0d[4] = { Wd0, Wd0 + (size_t)HH * HH, Wd0 + 2 * (size_t)HH * HH, Wd0 + 3 * (size_t)HH * HH };
    float* sb0 = sbW;  float* sb1 = sbW + HH;  float* sb2 = sbW + 2 * HH;  float* sb3 = sbW + 3 * HH;
    float* saP0 = saA; float* saP1 = saA + MM;

    // setup: quantize inputs and weights
    quant_x_kernel<<<MM / 8, 256>>>(x, X1, X0, saX);
    quant_w_kernel<<<HH / 8, 256>>>(W1, FF, HH, W1d[0], W0d[0], sb0);
    quant_w_kernel<<<HH / 8, 256>>>(W2, HH, HH, W1d[1], W0d[1], sb1);
    quant_w_kernel<<<HH / 8, 256>>>(W3, HH, HH, W1d[2], W0d[2], sb2);
    quant_w_kernel<<<OO / 8, 256>>>(W4, HH, OO, W1d[3], W0d[3], sb3);

    const dim3 gMid(HH / 128, MM / 128);   // (4, 608)
    const dim3 gLast(OO / 128, MM / 128);  // (2, 608)

    // Layer 1
    gemm_s8<FF, HH><<<gMid, 256, DSMEM_G>>>(X1, X0, saX, W1d[0], W0d[0], sb0, Hb);
    gat_agg_q<HH, true><<<BB, HH>>>(Hb, ei, as1, ad1, b1, Aa1, Aa0, saP0);
    // Layer 2
    gemm_s8<HH, HH><<<gMid, 256, DSMEM_G>>>(Aa1, Aa0, saP0, W1d[1], W0d[1], sb1, Hb);
    gat_agg_q<HH, true><<<BB, HH>>>(Hb, ei, as2, ad2, b2, Ab1, Ab0, saP1);
    // Layer 3
    gemm_s8<HH, HH><<<gMid, 256, DSMEM_G>>>(Ab1, Ab0, saP1, W1d[2], W0d[2], sb2, Hb);
    gat_agg_q<HH, true><<<BB, HH>>>(Hb, ei, as3, ad3, b3, Aa1, Aa0, saP0);
    // Layer 4 + fused head
    gemm_s8<HH, OO><<<gLast, 256, DSMEM_G>>>(Aa1, Aa0, saP0, W1d[3], W0d[3], sb3, Hb);
    gat_final<<<BB, OO>>>(Hb, ei, as4, ad4, b4, out, ws, bs);
}

// round 9
// speedup vs baseline: 3.1923x; 3.1923x over previous
#include <cuda_runtime.h>
#include <cuda_bf16.h>
#include <stdint.h>
#include <math.h>

// ---------------------------------------------------------------------------
// Problem constants
// ---------------------------------------------------------------------------
#define BB 4096
#define NN 19
#define EE 342
#define ET 361
#define FF 256
#define HH 512
#define OO 256
#define MM (BB * NN)      // 77824, divisible by 128

// ---------------------------------------------------------------------------
// Scratch (device globals)
// ---------------------------------------------------------------------------
__device__ __nv_bfloat16 g_Ahi[(size_t)MM * HH];
__device__ __nv_bfloat16 g_Alo[(size_t)MM * HH];
__device__ float         g_H  [(size_t)MM * HH];
__device__ __nv_bfloat16 g_Wh[4][HH * HH];   // transposed weight splits [N,K]
__device__ __nv_bfloat16 g_Wl[4][HH * HH];

// ---------------------------------------------------------------------------
// Helpers
// ---------------------------------------------------------------------------
__device__ __forceinline__ uint32_t smem_u32(const void* p) {
    uint32_t a;
    asm("{ .reg .u64 t; cvta.to.shared.u64 t, %1; cvt.u32.u64 %0, t; }"
        : "=r"(a) : "l"(p));
    return a;
}
// 64-byte-row swizzle (rows are 64B here)
#define SWZ64(o) ((o) ^ (((o) >> 3) & 0x30))

__device__ __forceinline__ void cp16(uint32_t s, const void* g) {
    asm volatile("cp.async.cg.shared.global [%0], [%1], 16;" :: "r"(s), "l"(g));
}

// ---------------------------------------------------------------------------
// Split kernels: fp32 -> (bf16 hi, bf16 lo)
// ---------------------------------------------------------------------------
__global__ void split_x_kernel(const float* __restrict__ x,
                               __nv_bfloat16* __restrict__ hi,
                               __nv_bfloat16* __restrict__ lo, size_t n) {
    size_t i = (size_t)blockIdx.x * 256 + threadIdx.x;
    if (i < n) {
        float v = x[i];
        __nv_bfloat16 h = __float2bfloat16(v);
        hi[i] = h;
        lo[i] = __float2bfloat16(v - __bfloat162float(h));
    }
}

// W [K,N] fp32 -> transposed splits [N,K] bf16
__global__ void split_w_kernel(const float* __restrict__ W,
                               __nv_bfloat16* __restrict__ hi,
                               __nv_bfloat16* __restrict__ lo, int K, int N) {
    int i = blockIdx.x * 256 + threadIdx.x;
    if (i < K * N) {
        int n = i / K, k = i % K;
        float v = W[(size_t)k * N + n];
        __nv_bfloat16 h = __float2bfloat16(v);
        hi[i] = h;
        lo[i] = __float2bfloat16(v - __bfloat162float(h));
    }
}

// ---------------------------------------------------------------------------
// mma.sync bf16x3 GEMM, pass-interleaved, 2 CTAs/SM:
//   H[M,NT] = Ah*Bh + Al*Bh + Ah*Bl  (fp32 accumulators).
// A: [M,K] bf16 row-major.  B: [NT,K] bf16 (N-major, K contiguous).
// CTA tile 128x128, 8 warps (2M x 4N), warp tile 64x32.
// K-chunks of 32 (64B rows, SW64 swizzle), 3-stage cp.async pipeline,
// stage = Ah(8K) | Al(8K) | Bh(8K) | Bl(8K) = 32KB;  3 stages = 96KB/CTA.
// ---------------------------------------------------------------------------
#define GEMM_STAGE 32768
#define GEMM_SMEM  (3 * GEMM_STAGE)

template <int K, int NT>
__global__ void __launch_bounds__(256, 2)
gemm_mma(const __nv_bfloat16* __restrict__ Ahi, const __nv_bfloat16* __restrict__ Alo,
         const __nv_bfloat16* __restrict__ Bhi, const __nv_bfloat16* __restrict__ Blo,
         float* __restrict__ Hout)
{
    extern __shared__ char smem[];
    const uint32_t sb = smem_u32(smem);
    const int tid  = threadIdx.x;
    const int wid  = tid >> 5;
    const int lane = tid & 31;
    const int bm = blockIdx.y * 128;
    const int bn = blockIdx.x * 128;
    const int wm = wid & 1;        // 0..1  (M halves of 64)
    const int wn = wid >> 1;       // 0..3  (N quarters of 32)

    constexpr int NCH = K / 32;    // K-chunks

    auto issue = [&](int ch) {
        const uint32_t st = sb + (uint32_t)(ch % 3) * GEMM_STAGE;
        const int kb = ch * 32;
        // each buffer: 128 rows x 64B = 512 x 16B units; 2 units/thread
#pragma unroll
        for (int i = 0; i < 2; i++) {
            int u = tid + i * 256;
            int rr = u >> 2, cc = u & 3;
            uint32_t so = SWZ64((uint32_t)(rr * 64 + cc * 16));
            size_t goA = (size_t)(bm + rr) * K + kb + cc * 8;
            size_t goB = (size_t)(bn + rr) * K + kb + cc * 8;
            cp16(st + so,          Ahi + goA);
            cp16(st + 8192u + so,  Alo + goA);
            cp16(st + 16384u + so, Bhi + goB);
            cp16(st + 24576u + so, Blo + goB);
        }
    };

    float acc[4][4][4] = {};

    issue(0);
    asm volatile("cp.async.commit_group;" ::: "memory");
    issue(1);
    asm volatile("cp.async.commit_group;" ::: "memory");

    for (int ch = 0; ch < NCH; ch++) {
        if (ch + 2 < NCH) {
            asm volatile("cp.async.wait_group 1;" ::: "memory");
            __syncthreads();
            issue(ch + 2);
            asm volatile("cp.async.commit_group;" ::: "memory");
        } else if (ch + 1 < NCH) {
            asm volatile("cp.async.wait_group 1;" ::: "memory");
            __syncthreads();
        } else {
            asm volatile("cp.async.wait_group 0;" ::: "memory");
            __syncthreads();
        }

        const uint32_t st  = sb + (uint32_t)(ch % 3) * GEMM_STAGE;
        const uint32_t sAh = st;
        const uint32_t sAl = st + 8192u;
        const uint32_t sBh = st + 16384u;
        const uint32_t sBl = st + 24576u;
#pragma unroll
        for (int kk = 0; kk < 2; kk++) {
            // B fragments (hi and lo): warp's 32 cols -> 4 n8-tiles -> 8 regs each
            uint32_t bh[8], bl[8];
#pragma unroll
            for (int g = 0; g < 2; g++) {
                int n = wn * 32 + g * 16 + ((lane >> 4) * 8) + (lane & 7);
                int c = kk * 2 + ((lane >> 3) & 1);
                uint32_t so = SWZ64((uint32_t)(n * 64 + c * 16));
                asm volatile(
                    "ldmatrix.sync.aligned.m8n8.x4.shared.b16 {%0,%1,%2,%3}, [%4];"
                    : "=r"(bh[g * 4 + 0]), "=r"(bh[g * 4 + 1]),
                      "=r"(bh[g * 4 + 2]), "=r"(bh[g * 4 + 3])
                    : "r"(sBh + so));
                asm volatile(
                    "ldmatrix.sync.aligned.m8n8.x4.shared.b16 {%0,%1,%2,%3}, [%4];"
                    : "=r"(bl[g * 4 + 0]), "=r"(bl[g * 4 + 1]),
                      "=r"(bl[g * 4 + 2]), "=r"(bl[g * 4 + 3])
                    : "r"(sBl + so));
            }
#pragma unroll
            for (int mt = 0; mt < 4; mt++) {
                uint32_t ah[4], al[4];
                int m = wm * 64 + mt * 16 + (lane & 15);
                int c = kk * 2 + (lane >> 4);
                uint32_t so = SWZ64((uint32_t)(m * 64 + c * 16));
                asm volatile(
                    "ldmatrix.sync.aligned.m8n8.x4.shared.b16 {%0,%1,%2,%3}, [%4];"
                    : "=r"(ah[0]), "=r"(ah[1]), "=r"(ah[2]), "=r"(ah[3])
                    : "r"(sAh + so));
                asm volatile(
                    "ldmatrix.sync.aligned.m8n8.x4.shared.b16 {%0,%1,%2,%3}, [%4];"
                    : "=r"(al[0]), "=r"(al[1]), "=r"(al[2]), "=r"(al[3])
                    : "r"(sAl + so));
#pragma unroll
                for (int nt = 0; nt < 4; nt++) {
                    float* d = acc[mt][nt];
                    asm volatile(
                        "mma.sync.aligned.m16n8k16.row.col.f32.bf16.bf16.f32 "
                        "{%0,%1,%2,%3}, {%4,%5,%6,%7}, {%8,%9}, {%0,%1,%2,%3};"
                        : "+f"(d[0]), "+f"(d[1]), "+f"(d[2]), "+f"(d[3])
                        : "r"(ah[0]), "r"(ah[1]), "r"(ah[2]), "r"(ah[3]),
                          "r"(bh[nt * 2]), "r"(bh[nt * 2 + 1]));
                    asm volatile(
                        "mma.sync.aligned.m16n8k16.row.col.f32.bf16.bf16.f32 "
                        "{%0,%1,%2,%3}, {%4,%5,%6,%7}, {%8,%9}, {%0,%1,%2,%3};"
                        : "+f"(d[0]), "+f"(d[1]), "+f"(d[2]), "+f"(d[3])
                        : "r"(al[0]), "r"(al[1]), "r"(al[2]), "r"(al[3]),
                          "r"(bh[nt * 2]), "r"(bh[nt * 2 + 1]));
                    asm volatile(
                        "mma.sync.aligned.m16n8k16.row.col.f32.bf16.bf16.f32 "
                        "{%0,%1,%2,%3}, {%4,%5,%6,%7}, {%8,%9}, {%0,%1,%2,%3};"
                        : "+f"(d[0]), "+f"(d[1]), "+f"(d[2]), "+f"(d[3])
                        : "r"(ah[0]), "r"(ah[1]), "r"(ah[2]), "r"(ah[3]),
                          "r"(bl[nt * 2]), "r"(bl[nt * 2 + 1]));
                }
            }
        }
        __syncthreads();
    }

    // Epilogue: fp32 stores.
#pragma unroll
    for (int mt = 0; mt < 4; mt++) {
        int row0 = bm + wm * 64 + mt * 16 + (lane >> 2);
#pragma unroll
        for (int nt = 0; nt < 4; nt++) {
            int col = bn + wn * 32 + nt * 8 + (lane & 3) * 2;
            *(float2*)(Hout + (size_t)row0 * NT + col) =
                make_float2(acc[mt][nt][0], acc[mt][nt][1]);
            *(float2*)(Hout + (size_t)(row0 + 8) * NT + col) =
                make_float2(acc[mt][nt][2], acc[mt][nt][3]);
        }
    }
}

// ---------------------------------------------------------------------------
// Attention + aggregation, dense-alpha. One CTA per graph, C threads.
// Softmax without max-subtraction (logits are O(few); exp safe; identical math).
// ---------------------------------------------------------------------------
template <int C>
__device__ __forceinline__ void attn_alpha(
    const float* __restrict__ hs, const int* __restrict__ ei,
    const float* __restrict__ a_s, const float* __restrict__ a_d,
    float* als, float* ald, float* nsum, float* alphaM, int t)
{
    {
        const int w = t >> 5, lane = t & 31, NW = C / 32;
        for (int n = w; n < NN; n += NW) {
            float s = 0.f, d = 0.f;
#pragma unroll
            for (int j = 0; j < C / 32; j++) {
                float h = hs[n * C + lane + 32 * j];
                s += h * __ldg(a_s + lane + 32 * j);
                d += h * __ldg(a_d + lane + 32 * j);
            }
#pragma unroll
            for (int o = 16; o; o >>= 1) {
                s += __shfl_xor_sync(0xffffffffu, s, o);
                d += __shfl_xor_sync(0xffffffffu, d, o);
            }
            if (lane == 0) { als[n] = s; ald[n] = d; }
        }
    }
    __syncthreads();
    for (int e = t; e < ET; e += C) {
        int se = (e < EE) ? ei[e] : (e - EE);
        int de = (e < EE) ? ei[EE + e] : (e - EE);
        float z = als[se] + ald[de];
        float lg = (z >= 0.f) ? z : 0.2f * z;
        atomicAdd(&nsum[de], __expf(lg));
    }
    __syncthreads();
    if (t < NN) nsum[t] = 1.f / nsum[t];
    __syncthreads();
    for (int e = t; e < ET; e += C) {
        int se = (e < EE) ? ei[e] : (e - EE);
        int de = (e < EE) ? ei[EE + e] : (e - EE);
        float z = als[se] + ald[de];
        float lg = (z >= 0.f) ? z : 0.2f * z;
        atomicAdd(&alphaM[de * NN + se], __expf(lg) * nsum[de]);
    }
    __syncthreads();
}

template <int C, bool RELU>
__global__ void __launch_bounds__(C) gat_agg_bf(
    const float* __restrict__ H, const int* __restrict__ ei,
    const float* __restrict__ a_s, const float* __restrict__ a_d,
    const float* __restrict__ bias,
    __nv_bfloat16* __restrict__ Ohi, __nv_bfloat16* __restrict__ Olo)
{
    __shared__ alignas(16) float hs[NN * C];
    __shared__ float als[NN], ald[NN], nsum[NN];
    __shared__ float alphaM[NN * NN];

    const int t = threadIdx.x;
    const size_t gbase = (size_t)blockIdx.x * NN * C;

    if (t < NN) nsum[t] = 0.f;
    for (int i = t; i < NN * NN; i += C) alphaM[i] = 0.f;
    {
        const float4* H4 = (const float4*)(H + gbase);
        float4* hs4 = (float4*)hs;
        for (int i = t; i < NN * C / 4; i += C) hs4[i] = H4[i];
    }
    __syncthreads();

    attn_alpha<C>(hs, ei, a_s, a_d, als, ald, nsum, alphaM, t);

    float hreg[NN];
#pragma unroll
    for (int s = 0; s < NN; s++) hreg[s] = hs[s * C + t];
    const float bc = bias[t];
#pragma unroll
    for (int n = 0; n < NN; n++) {
        float acc = 0.f;
#pragma unroll
        for (int s = 0; s < NN; s++) acc += alphaM[n * NN + s] * hreg[s];
        float v = acc + bc;
        if (RELU) v = fmaxf(v, 0.f);
        __nv_bfloat16 hi = __float2bfloat16(v);
        Ohi[gbase + (size_t)n * C + t] = hi;
        Olo[gbase + (size_t)n * C + t] = __float2bfloat16(v - __bfloat162float(hi));
    }
}

// Final layer: aggregation (no relu) + fused head
__global__ void __launch_bounds__(OO) gat_final(
    const float* __restrict__ H, const int* __restrict__ ei,
    const float* __restrict__ a_s, const float* __restrict__ a_d,
    const float* __restrict__ bias, float* __restrict__ outp,
    const float* __restrict__ ws, const float* __restrict__ bsc)
{
    constexpr int C = OO;
    __shared__ alignas(16) float hs[NN * C];
    __shared__ float als[NN], ald[NN], nsum[NN];
    __shared__ float alphaM[NN * NN];
    __shared__ alignas(16) float outbuf[NN * C];
    __shared__ float pbuf[C];

    const int t = threadIdx.x;
    const size_t gbase = (size_t)blockIdx.x * NN * C;

    if (t < NN) nsum[t] = 0.f;
    for (int i = t; i < NN * NN; i += C) alphaM[i] = 0.f;
    {
        const float4* H4 = (const float4*)(H + gbase);
        float4* hs4 = (float4*)hs;
        for (int i = t; i < NN * C / 4; i += C) hs4[i] = H4[i];
    }
    __syncthreads();

    attn_alpha<C>(hs, ei, a_s, a_d, als, ald, nsum, alphaM, t);

    float hreg[NN];
#pragma unroll
    for (int s = 0; s < NN; s++) hreg[s] = hs[s * C + t];
    const float bc = bias[t];
#pragma unroll
    for (int n = 0; n < NN; n++) {
        float acc = 0.f;
#pragma unroll
        for (int s = 0; s < NN; s++) acc += alphaM[n * NN + s] * hreg[s];
        outbuf[n * C + t] = acc + bc;
    }
    __syncthreads();

    {
        float pv = 0.f;
#pragma unroll
        for (int n = 0; n < NN; n++) pv += ws[n] * outbuf[n * C + t];
        pbuf[t] = pv;
    }
    __syncthreads();
    {
        const int w = t >> 5, lane = t & 31, NW = C / 32;
        const float bv = bsc[0];
        for (int n = w; n < NN; n += NW) {
            float s = 0.f;
#pragma unroll
            for (int j = 0; j < C / 32; j++)
                s += outbuf[n * C + lane + 32 * j] * pbuf[lane + 32 * j];
#pragma unroll
            for (int o = 16; o; o >>= 1)
                s += __shfl_xor_sync(0xffffffffu, s, o);
            if (lane == 0)
                outp[(size_t)blockIdx.x * NN + n] = 1.f / (1.f + __expf(-(s + bv)));
        }
    }
}

// ---------------------------------------------------------------------------
// Launch
// ---------------------------------------------------------------------------
extern "C" void kernel_launch(void* const* d_in, const int* in_sizes, int n_in,
                              void* d_out, int out_size)
{
    (void)in_sizes; (void)n_in; (void)out_size;
    const float* x   = (const float*)d_in[0];
    const int*   ei  = (const int*)  d_in[1];
    const float* W1  = (const float*)d_in[3];
    const float* as1 = (const float*)d_in[4];
    const float* ad1 = (const float*)d_in[5];
    const float* b1  = (const float*)d_in[6];
    const float* W2  = (const float*)d_in[7];
    const float* as2 = (const float*)d_in[8];
    const float* ad2 = (const float*)d_in[9];
    const float* b2  = (const float*)d_in[10];
    const float* W3  = (const float*)d_in[11];
    const float* as3 = (const float*)d_in[12];
    const float* ad3 = (const float*)d_in[13];
    const float* b3  = (const float*)d_in[14];
    const float* W4  = (const float*)d_in[15];
    const float* as4 = (const float*)d_in[16];
    const float* ad4 = (const float*)d_in[17];
    const float* b4  = (const float*)d_in[18];
    const float* ws  = (const float*)d_in[19];
    const float* bs  = (const float*)d_in[20];
    float* out = (float*)d_out;

    __nv_bfloat16 *Ahi, *Alo, *Wh, *Wl;
    float* Hb;
    cudaGetSymbolAddress((void**)&Ahi, g_Ahi);
    cudaGetSymbolAddress((void**)&Alo, g_Alo);
    cudaGetSymbolAddress((void**)&Hb,  g_H);
    cudaGetSymbolAddress((void**)&Wh,  g_Wh);
    cudaGetSymbolAddress((void**)&Wl,  g_Wl);

    cudaFuncSetAttribute(gemm_mma<FF, HH>, cudaFuncAttributeMaxDynamicSharedMemorySize, GEMM_SMEM);
    cudaFuncSetAttribute(gemm_mma<HH, HH>, cudaFuncAttributeMaxDynamicSharedMemorySize, GEMM_SMEM);
    cudaFuncSetAttribute(gemm_mma<HH, OO>, cudaFuncAttributeMaxDynamicSharedMemorySize, GEMM_SMEM);

    __nv_bfloat16* Wh0 = Wh + 0 * (HH * HH);
    __nv_bfloat16* Wh1 = Wh + 1 * (HH * HH);
    __nv_bfloat16* Wh2 = Wh + 2 * (HH * HH);
    __nv_bfloat16* Wh3 = Wh + 3 * (HH * HH);
    __nv_bfloat16* Wl0 = Wl + 0 * (HH * HH);
    __nv_bfloat16* Wl1 = Wl + 1 * (HH * HH);
    __nv_bfloat16* Wl2 = Wl + 2 * (HH * HH);
    __nv_bfloat16* Wl3 = Wl + 3 * (HH * HH);

    split_x_kernel<<<(MM * FF + 255) / 256, 256>>>(x, Ahi, Alo, (size_t)MM * FF);
    split_w_kernel<<<(FF * HH + 255) / 256, 256>>>(W1, Wh0, Wl0, FF, HH);
    split_w_kernel<<<(HH * HH + 255) / 256, 256>>>(W2, Wh1, Wl1, HH, HH);
    split_w_kernel<<<(HH * HH + 255) / 256, 256>>>(W3, Wh2, Wl2, HH, HH);
    split_w_kernel<<<(HH * OO + 255) / 256, 256>>>(W4, Wh3, Wl3, HH, OO);

    const dim3 g2(HH / 128, MM / 128);   // (4, 608)
    const dim3 g1(OO / 128, MM / 128);   // (2, 608)

    // Layer 1
    gemm_mma<FF, HH><<<g2, 256, GEMM_SMEM>>>(Ahi, Alo, Wh0, Wl0, Hb);
    gat_agg_bf<HH, true><<<BB, HH>>>(Hb, ei, as1, ad1, b1, Ahi, Alo);
    // Layer 2
    gemm_mma<HH, HH><<<g2, 256, GEMM_SMEM>>>(Ahi, Alo, Wh1, Wl1, Hb);
    gat_agg_bf<HH, true><<<BB, HH>>>(Hb, ei, as2, ad2, b2, Ahi, Alo);
    // Layer 3
    gemm_mma<HH, HH><<<g2, 256, GEMM_SMEM>>>(Ahi, Alo, Wh2, Wl2, Hb);
    gat_agg_bf<HH, true><<<BB, HH>>>(Hb, ei, as3, ad3, b3, Ahi, Alo);
    // Layer 4 + fused head
    gemm_mma<HH, OO><<<g1, 256, GEMM_SMEM>>>(Ahi, Alo, Wh3, Wl3, Hb);
    gat_final<<<BB, OO>>>(Hb, ei, as4, ad4, b4, out, ws, bs);
}

// round 10
// speedup vs baseline: 3.2506x; 1.0182x over previous
#include <cuda_runtime.h>
#include <cuda_bf16.h>
#include <stdint.h>
#include <math.h>

// ---------------------------------------------------------------------------
// Problem constants
// ---------------------------------------------------------------------------
#define BB 4096
#define NN 19
#define EE 342
#define ET 361
#define FF 256
#define HH 512
#define OO 256
#define MM (BB * NN)      // 77824, divisible by 128

// ---------------------------------------------------------------------------
// Scratch (device globals)
// ---------------------------------------------------------------------------
__device__ __nv_bfloat16 g_Ahi[(size_t)MM * HH];
__device__ __nv_bfloat16 g_Alo[(size_t)MM * HH];
__device__ float         g_H  [(size_t)MM * HH];
__device__ __nv_bfloat16 g_Wh[4][HH * HH];   // transposed weight splits [N,K]
__device__ __nv_bfloat16 g_Wl[4][HH * HH];

// ---------------------------------------------------------------------------
// Helpers
// ---------------------------------------------------------------------------
__device__ __forceinline__ uint32_t smem_u32(const void* p) {
    uint32_t a;
    asm("{ .reg .u64 t; cvta.to.shared.u64 t, %1; cvt.u32.u64 %0, t; }"
        : "=r"(a) : "l"(p));
    return a;
}
// 64-byte-row swizzle (rows are 64B here)
#define SWZ64(o) ((o) ^ (((o) >> 3) & 0x30))

__device__ __forceinline__ void cp16(uint32_t s, const void* g) {
    asm volatile("cp.async.cg.shared.global [%0], [%1], 16;" :: "r"(s), "l"(g));
}

// ---------------------------------------------------------------------------
// Split kernels: fp32 -> (bf16 hi, bf16 lo)
// ---------------------------------------------------------------------------
__global__ void split_x_kernel(const float* __restrict__ x,
                               __nv_bfloat16* __restrict__ hi,
                               __nv_bfloat16* __restrict__ lo, size_t n) {
    size_t i = (size_t)blockIdx.x * 256 + threadIdx.x;
    if (i < n) {
        float v = x[i];
        __nv_bfloat16 h = __float2bfloat16(v);
        hi[i] = h;
        lo[i] = __float2bfloat16(v - __bfloat162float(h));
    }
}

// W [K,N] fp32 -> transposed splits [N,K] bf16
__global__ void split_w_kernel(const float* __restrict__ W,
                               __nv_bfloat16* __restrict__ hi,
                               __nv_bfloat16* __restrict__ lo, int K, int N) {
    int i = blockIdx.x * 256 + threadIdx.x;
    if (i < K * N) {
        int n = i / K, k = i % K;
        float v = W[(size_t)k * N + n];
        __nv_bfloat16 h = __float2bfloat16(v);
        hi[i] = h;
        lo[i] = __float2bfloat16(v - __bfloat162float(h));
    }
}

// ---------------------------------------------------------------------------
// mma.sync bf16x3 GEMM, pass-interleaved, 2 CTAs/SM:
//   H[M,NT] = Ah*Bh + Al*Bh + Ah*Bl  (fp32 accumulators).
// A: [M,K] bf16 row-major.  B: [NT,K] bf16 (N-major, K contiguous).
// CTA tile 128x128, 8 warps (2M x 4N), warp tile 64x32.
// K-chunks of 32 (64B rows, SW64 swizzle), 3-stage cp.async pipeline,
// stage = Ah(8K) | Al(8K) | Bh(8K) | Bl(8K) = 32KB;  3 stages = 96KB/CTA.
// ---------------------------------------------------------------------------
#define GEMM_STAGE 32768
#define GEMM_SMEM  (3 * GEMM_STAGE)

template <int K, int NT>
__global__ void __launch_bounds__(256, 2)
gemm_mma(const __nv_bfloat16* __restrict__ Ahi, const __nv_bfloat16* __restrict__ Alo,
         const __nv_bfloat16* __restrict__ Bhi, const __nv_bfloat16* __restrict__ Blo,
         float* __restrict__ Hout)
{
    extern __shared__ char smem[];
    const uint32_t sb = smem_u32(smem);
    const int tid  = threadIdx.x;
    const int wid  = tid >> 5;
    const int lane = tid & 31;
    const int bm = blockIdx.y * 128;
    const int bn = blockIdx.x * 128;
    const int wm = wid & 1;        // 0..1  (M halves of 64)
    const int wn = wid >> 1;       // 0..3  (N quarters of 32)

    constexpr int NCH = K / 32;    // K-chunks

    auto issue = [&](int ch) {
        const uint32_t st = sb + (uint32_t)(ch % 3) * GEMM_STAGE;
        const int kb = ch * 32;
        // each buffer: 128 rows x 64B = 512 x 16B units; 2 units/thread
#pragma unroll
        for (int i = 0; i < 2; i++) {
            int u = tid + i * 256;
            int rr = u >> 2, cc = u & 3;
            uint32_t so = SWZ64((uint32_t)(rr * 64 + cc * 16));
            size_t goA = (size_t)(bm + rr) * K + kb + cc * 8;
            size_t goB = (size_t)(bn + rr) * K + kb + cc * 8;
            cp16(st + so,          Ahi + goA);
            cp16(st + 8192u + so,  Alo + goA);
            cp16(st + 16384u + so, Bhi + goB);
            cp16(st + 24576u + so, Blo + goB);
        }
    };

    float acc[4][4][4] = {};

    issue(0);
    asm volatile("cp.async.commit_group;" ::: "memory");
    issue(1);
    asm volatile("cp.async.commit_group;" ::: "memory");

    for (int ch = 0; ch < NCH; ch++) {
        if (ch + 2 < NCH) {
            asm volatile("cp.async.wait_group 1;" ::: "memory");
            __syncthreads();
            issue(ch + 2);
            asm volatile("cp.async.commit_group;" ::: "memory");
        } else if (ch + 1 < NCH) {
            asm volatile("cp.async.wait_group 1;" ::: "memory");
            __syncthreads();
        } else {
            asm volatile("cp.async.wait_group 0;" ::: "memory");
            __syncthreads();
        }

        const uint32_t st  = sb + (uint32_t)(ch % 3) * GEMM_STAGE;
        const uint32_t sAh = st;
        const uint32_t sAl = st + 8192u;
        const uint32_t sBh = st + 16384u;
        const uint32_t sBl = st + 24576u;
#pragma unroll
        for (int kk = 0; kk < 2; kk++) {
            // B fragments (hi and lo): warp's 32 cols -> 4 n8-tiles -> 8 regs each
            uint32_t bh[8], bl[8];
#pragma unroll
            for (int g = 0; g < 2; g++) {
                int n = wn * 32 + g * 16 + ((lane >> 4) * 8) + (lane & 7);
                int c = kk * 2 + ((lane >> 3) & 1);
                uint32_t so = SWZ64((uint32_t)(n * 64 + c * 16));
                asm volatile(
                    "ldmatrix.sync.aligned.m8n8.x4.shared.b16 {%0,%1,%2,%3}, [%4];"
                    : "=r"(bh[g * 4 + 0]), "=r"(bh[g * 4 + 1]),
                      "=r"(bh[g * 4 + 2]), "=r"(bh[g * 4 + 3])
                    : "r"(sBh + so));
                asm volatile(
                    "ldmatrix.sync.aligned.m8n8.x4.shared.b16 {%0,%1,%2,%3}, [%4];"
                    : "=r"(bl[g * 4 + 0]), "=r"(bl[g * 4 + 1]),
                      "=r"(bl[g * 4 + 2]), "=r"(bl[g * 4 + 3])
                    : "r"(sBl + so));
            }
#pragma unroll
            for (int mt = 0; mt < 4; mt++) {
                uint32_t ah[4], al[4];
                int m = wm * 64 + mt * 16 + (lane & 15);
                int c = kk * 2 + (lane >> 4);
                uint32_t so = SWZ64((uint32_t)(m * 64 + c * 16));
                asm volatile(
                    "ldmatrix.sync.aligned.m8n8.x4.shared.b16 {%0,%1,%2,%3}, [%4];"
                    : "=r"(ah[0]), "=r"(ah[1]), "=r"(ah[2]), "=r"(ah[3])
                    : "r"(sAh + so));
                asm volatile(
                    "ldmatrix.sync.aligned.m8n8.x4.shared.b16 {%0,%1,%2,%3}, [%4];"
                    : "=r"(al[0]), "=r"(al[1]), "=r"(al[2]), "=r"(al[3])
                    : "r"(sAl + so));
#pragma unroll
                for (int nt = 0; nt < 4; nt++) {
                    float* d = acc[mt][nt];
                    asm volatile(
                        "mma.sync.aligned.m16n8k16.row.col.f32.bf16.bf16.f32 "
                        "{%0,%1,%2,%3}, {%4,%5,%6,%7}, {%8,%9}, {%0,%1,%2,%3};"
                        : "+f"(d[0]), "+f"(d[1]), "+f"(d[2]), "+f"(d[3])
                        : "r"(ah[0]), "r"(ah[1]), "r"(ah[2]), "r"(ah[3]),
                          "r"(bh[nt * 2]), "r"(bh[nt * 2 + 1]));
                    asm volatile(
                        "mma.sync.aligned.m16n8k16.row.col.f32.bf16.bf16.f32 "
                        "{%0,%1,%2,%3}, {%4,%5,%6,%7}, {%8,%9}, {%0,%1,%2,%3};"
                        : "+f"(d[0]), "+f"(d[1]), "+f"(d[2]), "+f"(d[3])
                        : "r"(al[0]), "r"(al[1]), "r"(al[2]), "r"(al[3]),
                          "r"(bh[nt * 2]), "r"(bh[nt * 2 + 1]));
                    asm volatile(
                        "mma.sync.aligned.m16n8k16.row.col.f32.bf16.bf16.f32 "
                        "{%0,%1,%2,%3}, {%4,%5,%6,%7}, {%8,%9}, {%0,%1,%2,%3};"
                        : "+f"(d[0]), "+f"(d[1]), "+f"(d[2]), "+f"(d[3])
                        : "r"(ah[0]), "r"(ah[1]), "r"(ah[2]), "r"(ah[3]),
                          "r"(bl[nt * 2]), "r"(bl[nt * 2 + 1]));
                }
            }
        }
        __syncthreads();
    }

    // Epilogue: fp32 stores.
#pragma unroll
    for (int mt = 0; mt < 4; mt++) {
        int row0 = bm + wm * 64 + mt * 16 + (lane >> 2);
#pragma unroll
        for (int nt = 0; nt < 4; nt++) {
            int col = bn + wn * 32 + nt * 8 + (lane & 3) * 2;
            *(float2*)(Hout + (size_t)row0 * NT + col) =
                make_float2(acc[mt][nt][0], acc[mt][nt][1]);
            *(float2*)(Hout + (size_t)(row0 + 8) * NT + col) =
                make_float2(acc[mt][nt][2], acc[mt][nt][3]);
        }
    }
}

// ---------------------------------------------------------------------------
// Attention + aggregation, dense-alpha. One CTA per graph, C threads.
// Softmax without max-subtraction; exp cached in smem edge buffer.
// ---------------------------------------------------------------------------
template <int C>
__device__ __forceinline__ void attn_alpha(
    const float* __restrict__ hs, const int* __restrict__ ei,
    const float* __restrict__ a_s, const float* __restrict__ a_d,
    float* als, float* ald, float* nsum, float* ebuf, float* alphaM, int t)
{
    {
        const int w = t >> 5, lane = t & 31, NW = C / 32;
        for (int n = w; n < NN; n += NW) {
            float s = 0.f, d = 0.f;
#pragma unroll
            for (int j = 0; j < C / 32; j++) {
                float h = hs[n * C + lane + 32 * j];
                s += h * __ldg(a_s + lane + 32 * j);
                d += h * __ldg(a_d + lane + 32 * j);
            }
#pragma unroll
            for (int o = 16; o; o >>= 1) {
                s += __shfl_xor_sync(0xffffffffu, s, o);
                d += __shfl_xor_sync(0xffffffffu, d, o);
            }
            if (lane == 0) { als[n] = s; ald[n] = d; }
        }
    }
    __syncthreads();
    for (int e = t; e < ET; e += C) {
        int se = (e < EE) ? ei[e] : (e - EE);
        int de = (e < EE) ? ei[EE + e] : (e - EE);
        float z = als[se] + ald[de];
        float lg = (z >= 0.f) ? z : 0.2f * z;
        float ex = __expf(lg);
        ebuf[e] = ex;
        atomicAdd(&nsum[de], ex);
    }
    __syncthreads();
    if (t < NN) nsum[t] = 1.f / nsum[t];
    __syncthreads();
    for (int e = t; e < ET; e += C) {
        int se = (e < EE) ? ei[e] : (e - EE);
        int de = (e < EE) ? ei[EE + e] : (e - EE);
        atomicAdd(&alphaM[de * NN + se], ebuf[e] * nsum[de]);
    }
    __syncthreads();
}

template <int C, bool RELU>
__global__ void __launch_bounds__(C) gat_agg_bf(
    const float* __restrict__ H, const int* __restrict__ ei,
    const float* __restrict__ a_s, const float* __restrict__ a_d,
    const float* __restrict__ bias,
    __nv_bfloat16* __restrict__ Ohi, __nv_bfloat16* __restrict__ Olo)
{
    __shared__ alignas(16) float hs[NN * C];
    __shared__ float als[NN], ald[NN], nsum[NN];
    __shared__ float ebuf[ET];
    __shared__ float alphaM[NN * NN];

    const int t = threadIdx.x;
    const size_t gbase = (size_t)blockIdx.x * NN * C;

    if (t < NN) nsum[t] = 0.f;
    for (int i = t; i < NN * NN; i += C) alphaM[i] = 0.f;
    {
        const float4* H4 = (const float4*)(H + gbase);
        float4* hs4 = (float4*)hs;
        for (int i = t; i < NN * C / 4; i += C) hs4[i] = H4[i];
    }
    __syncthreads();

    attn_alpha<C>(hs, ei, a_s, a_d, als, ald, nsum, ebuf, alphaM, t);

    float hreg[NN];
#pragma unroll
    for (int s = 0; s < NN; s++) hreg[s] = hs[s * C + t];
    const float bc = bias[t];
#pragma unroll
    for (int n = 0; n < NN; n++) {
        float acc = 0.f;
#pragma unroll
        for (int s = 0; s < NN; s++) acc += alphaM[n * NN + s] * hreg[s];
        float v = acc + bc;
        if (RELU) v = fmaxf(v, 0.f);
        __nv_bfloat16 hi = __float2bfloat16(v);
        Ohi[gbase + (size_t)n * C + t] = hi;
        Olo[gbase + (size_t)n * C + t] = __float2bfloat16(v - __bfloat162float(hi));
    }
}

// Final layer: aggregation (no relu) + fused head
__global__ void __launch_bounds__(OO) gat_final(
    const float* __restrict__ H, const int* __restrict__ ei,
    const float* __restrict__ a_s, const float* __restrict__ a_d,
    const float* __restrict__ bias, float* __restrict__ outp,
    const float* __restrict__ ws, const float* __restrict__ bsc)
{
    constexpr int C = OO;
    __shared__ alignas(16) float hs[NN * C];
    __shared__ float als[NN], ald[NN], nsum[NN];
    __shared__ float ebuf[ET];
    __shared__ float alphaM[NN * NN];
    __shared__ alignas(16) float outbuf[NN * C];
    __shared__ float pbuf[C];

    const int t = threadIdx.x;
    const size_t gbase = (size_t)blockIdx.x * NN * C;

    if (t < NN) nsum[t] = 0.f;
    for (int i = t; i < NN * NN; i += C) alphaM[i] = 0.f;
    {
        const float4* H4 = (const float4*)(H + gbase);
        float4* hs4 = (float4*)hs;
        for (int i = t; i < NN * C / 4; i += C) hs4[i] = H4[i];
    }
    __syncthreads();

    attn_alpha<C>(hs, ei, a_s, a_d, als, ald, nsum, ebuf, alphaM, t);

    float hreg[NN];
#pragma unroll
    for (int s = 0; s < NN; s++) hreg[s] = hs[s * C + t];
    const float bc = bias[t];
#pragma unroll
    for (int n = 0; n < NN; n++) {
        float acc = 0.f;
#pragma unroll
        for (int s = 0; s < NN; s++) acc += alphaM[n * NN + s] * hreg[s];
        outbuf[n * C + t] = acc + bc;
    }
    __syncthreads();

    {
        float pv = 0.f;
#pragma unroll
        for (int n = 0; n < NN; n++) pv += ws[n] * outbuf[n * C + t];
        pbuf[t] = pv;
    }
    __syncthreads();
    {
        const int w = t >> 5, lane = t & 31, NW = C / 32;
        const float bv = bsc[0];
        for (int n = w; n < NN; n += NW) {
            float s = 0.f;
#pragma unroll
            for (int j = 0; j < C / 32; j++)
                s += outbuf[n * C + lane + 32 * j] * pbuf[lane + 32 * j];
#pragma unroll
            for (int o = 16; o; o >>= 1)
                s += __shfl_xor_sync(0xffffffffu, s, o);
            if (lane == 0)
                outp[(size_t)blockIdx.x * NN + n] = 1.f / (1.f + __expf(-(s + bv)));
        }
    }
}

// ---------------------------------------------------------------------------
// Launch.  Setup kernels ordered so the 5th launch overall (ncu capture slot,
// accounting for the harness's poison kernel at slot 0) is gemm_mma layer 1.
// ---------------------------------------------------------------------------
extern "C" void kernel_launch(void* const* d_in, const int* in_sizes, int n_in,
                              void* d_out, int out_size)
{
    (void)in_sizes; (void)n_in; (void)out_size;
    const float* x   = (const float*)d_in[0];
    const int*   ei  = (const int*)  d_in[1];
    const float* W1  = (const float*)d_in[3];
    const float* as1 = (const float*)d_in[4];
    const float* ad1 = (const float*)d_in[5];
    const float* b1  = (const float*)d_in[6];
    const float* W2  = (const float*)d_in[7];
    const float* as2 = (const float*)d_in[8];
    const float* ad2 = (const float*)d_in[9];
    const float* b2  = (const float*)d_in[10];
    const float* W3  = (const float*)d_in[11];
    const float* as3 = (const float*)d_in[12];
    const float* ad3 = (const float*)d_in[13];
    const float* b3  = (const float*)d_in[14];
    const float* W4  = (const float*)d_in[15];
    const float* as4 = (const float*)d_in[16];
    const float* ad4 = (const float*)d_in[17];
    const float* b4  = (const float*)d_in[18];
    const float* ws  = (const float*)d_in[19];
    const float* bs  = (const float*)d_in[20];
    float* out = (float*)d_out;

    __nv_bfloat16 *Ahi, *Alo, *Wh, *Wl;
    float* Hb;
    cudaGetSymbolAddress((void**)&Ahi, g_Ahi);
    cudaGetSymbolAddress((void**)&Alo, g_Alo);
    cudaGetSymbolAddress((void**)&Hb,  g_H);
    cudaGetSymbolAddress((void**)&Wh,  g_Wh);
    cudaGetSymbolAddress((void**)&Wl,  g_Wl);

    cudaFuncSetAttribute(gemm_mma<FF, HH>, cudaFuncAttributeMaxDynamicSharedMemorySize, GEMM_SMEM);
    cudaFuncSetAttribute(gemm_mma<HH, HH>, cudaFuncAttributeMaxDynamicSharedMemorySize, GEMM_SMEM);
    cudaFuncSetAttribute(gemm_mma<HH, OO>, cudaFuncAttributeMaxDynamicSharedMemorySize, GEMM_SMEM);

    __nv_bfloat16* Wh0 = Wh + 0 * (HH * HH);
    __nv_bfloat16* Wh1 = Wh + 1 * (HH * HH);
    __nv_bfloat16* Wh2 = Wh + 2 * (HH * HH);
    __nv_bfloat16* Wh3 = Wh + 3 * (HH * HH);
    __nv_bfloat16* Wl0 = Wl + 0 * (HH * HH);
    __nv_bfloat16* Wl1 = Wl + 1 * (HH * HH);
    __nv_bfloat16* Wl2 = Wl + 2 * (HH * HH);
    __nv_bfloat16* Wl3 = Wl + 3 * (HH * HH);

    const dim3 g2(HH / 128, MM / 128);   // (4, 608)
    const dim3 g1(OO / 128, MM / 128);   // (2, 608)

    // Setup, ordered for ncu capture: launches 1-4 are setup, 5 = gemm L1.
    split_w_kernel<<<(HH * HH + 255) / 256, 256>>>(W2, Wh1, Wl1, HH, HH);  // 1
    split_w_kernel<<<(HH * HH + 255) / 256, 256>>>(W3, Wh2, Wl2, HH, HH);  // 2
    split_x_kernel<<<(MM * FF + 255) / 256, 256>>>(x, Ahi, Alo, (size_t)MM * FF); // 3
    split_w_kernel<<<(FF * HH + 255) / 256, 256>>>(W1, Wh0, Wl0, FF, HH);  // 4

    // Layer 1  (launch 5 — ncu capture target)
    gemm_mma<FF, HH><<<g2, 256, GEMM_SMEM>>>(Ahi, Alo, Wh0, Wl0, Hb);
    split_w_kernel<<<(HH * OO + 255) / 256, 256>>>(W4, Wh3, Wl3, HH, OO);  // 6
    gat_agg_bf<HH, true><<<BB, HH>>>(Hb, ei, as1, ad1, b1, Ahi, Alo);
    // Layer 2
    gemm_mma<HH, HH><<<g2, 256, GEMM_SMEM>>>(Ahi, Alo, Wh1, Wl1, Hb);
    gat_agg_bf<HH, true><<<BB, HH>>>(Hb, ei, as2, ad2, b2, Ahi, Alo);
    // Layer 3
    gemm_mma<HH, HH><<<g2, 256, GEMM_SMEM>>>(Ahi, Alo, Wh2, Wl2, Hb);
    gat_agg_bf<HH, true><<<BB, HH>>>(Hb, ei, as3, ad3, b3, Ahi, Alo);
    // Layer 4 + fused head
    gemm_mma<HH, OO><<<g1, 256, GEMM_SMEM>>>(Ahi, Alo, Wh3, Wl3, Hb);
    gat_final<<<BB, OO>>>(Hb, ei, as4, ad4, b4, out, ws, bs);
}